// round 2
// baseline (speedup 1.0000x reference)
#include <cuda_runtime.h>
#include <cstdint>

// =====================================================================
// Device scratch (allocation-free: __device__ globals)
// =====================================================================
__device__ float g_act[33554432];   // 32768 x 1024, tf32-rounded v*x_sp
__device__ float g_wt[1048576];     // 1024 x 1024,  tf32-rounded weight

// =====================================================================
// Small helpers (base ISA only — NO tcgen05 / NO 'a'-suffix features)
// =====================================================================
__device__ __forceinline__ uint32_t f2tf32(float f) {
    uint32_t u;
    asm("cvt.rna.tf32.f32 %0, %1;" : "=r"(u) : "f"(f));
    return u;
}

__device__ __forceinline__ void cp16(void* s, const void* g) {
    uint32_t sa = (uint32_t)__cvta_generic_to_shared(s);
    asm volatile("cp.async.cg.shared.global [%0], [%1], 16;"
                 :: "r"(sa), "l"(g) : "memory");
}
__device__ __forceinline__ void cp_commit() {
    asm volatile("cp.async.commit_group;" ::: "memory");
}
template <int N>
__device__ __forceinline__ void cp_wait() {
    asm volatile("cp.async.wait_group %0;" :: "n"(N) : "memory");
}

// =====================================================================
// Kernel 1: 2:4 prune + variance rescale + tf32 round  (one block / row)
// =====================================================================
__global__ void __launch_bounds__(256) prep_kernel(const float* __restrict__ x,
                                                   float* __restrict__ act) {
    const int row = blockIdx.x;
    const int t   = threadIdx.x;           // 256 threads, 1 group of 4 each
    const float4 g = reinterpret_cast<const float4*>(x + (size_t)row * 1024)[t];

    float v0 = g.x, v1 = g.y, v2 = g.z, v3 = g.w;
    float a0 = fabsf(v0), a1 = fabsf(v1), a2 = fabsf(v2), a3 = fabsf(v3);
    // rank = #elements strictly greater (+ earlier-index ties); keep top-2
    int r0 = (a1 >  a0) + (a2 >  a0) + (a3 >  a0);
    int r1 = (a0 >= a1) + (a2 >  a1) + (a3 >  a1);
    int r2 = (a0 >= a2) + (a1 >= a2) + (a3 >  a2);
    int r3 = (a0 >= a3) + (a1 >= a3) + (a2 >= a3);
    float p0 = (r0 < 2) ? v0 : 0.f;
    float p1 = (r1 < 2) ? v1 : 0.f;
    float p2 = (r2 < 2) ? v2 : 0.f;
    float p3 = (r3 < 2) ? v3 : 0.f;

    float s   = v0 + v1 + v2 + v3;
    float ss  = v0*v0 + v1*v1 + v2*v2 + v3*v3;
    float ps  = p0 + p1 + p2 + p3;
    float pss = p0*p0 + p1*p1 + p2*p2 + p3*p3;

    #pragma unroll
    for (int off = 16; off; off >>= 1) {
        s   += __shfl_xor_sync(0xFFFFFFFFu, s,   off);
        ss  += __shfl_xor_sync(0xFFFFFFFFu, ss,  off);
        ps  += __shfl_xor_sync(0xFFFFFFFFu, ps,  off);
        pss += __shfl_xor_sync(0xFFFFFFFFu, pss, off);
    }
    __shared__ float4 sh[8];
    __shared__ float  scale_sh;
    if ((t & 31) == 0) sh[t >> 5] = make_float4(s, ss, ps, pss);
    __syncthreads();
    if (t == 0) {
        float S = 0.f, SS = 0.f, PS = 0.f, PSS = 0.f;
        #pragma unroll
        for (int i = 0; i < 8; i++) {
            S += sh[i].x; SS += sh[i].y; PS += sh[i].z; PSS += sh[i].w;
        }
        float varx = (SS  - S  * S  * (1.f / 1024.f)) * (1.f / 1023.f);
        float varp = (PSS - PS * PS * (1.f / 1024.f)) * (1.f / 1023.f);
        varp = fmaxf(varp, 1e-9f);
        scale_sh = sqrtf(varx / varp);
    }
    __syncthreads();
    const float sc = scale_sh;

    float4 o;
    o.x = __uint_as_float(f2tf32(sc * p0));
    o.y = __uint_as_float(f2tf32(sc * p1));
    o.z = __uint_as_float(f2tf32(sc * p2));
    o.w = __uint_as_float(f2tf32(sc * p3));
    reinterpret_cast<float4*>(act + (size_t)row * 1024)[t] = o;
}

// =====================================================================
// Kernel 2: weight -> tf32-rounded scratch
// =====================================================================
__global__ void __launch_bounds__(256) wconv_kernel(const float* __restrict__ w,
                                                    float* __restrict__ o) {
    int i = blockIdx.x * 256 + threadIdx.x;
    o[i] = __uint_as_float(f2tf32(w[i]));
}

// =====================================================================
// Kernel 3: tf32 mma.sync GEMM.  C[32768,1024] = A[32768,1024] @ W[1024,1024]^T
// CTA tile 256x128, K-chunk 32, 3-stage cp.async pipeline.
// 8 warps, warp tile 64x64 (m16n8k8 fragments: 4 m-tiles x 8 n-tiles).
// SMEM rows padded to 36 floats -> conflict-free fragment loads.
// =====================================================================
static constexpr int BM = 256;
static constexpr int BN = 128;
static constexpr int BK = 32;
static constexpr int STAGES = 3;
static constexpr int LDS_ = 36;                       // padded row stride (floats)
static constexpr int A_FLOATS = BM * LDS_;            // 9216
static constexpr int B_FLOATS = BN * LDS_;            // 4608
static constexpr int STAGE_FLOATS = A_FLOATS + B_FLOATS;  // 13824
static constexpr unsigned SMEM_DYN = STAGES * STAGE_FLOATS * 4;  // 165888 B
static constexpr int KTILES = 1024 / BK;              // 32

__device__ __forceinline__ void mma_tf32(float* d, const uint32_t* a,
                                         const uint32_t* b) {
    asm volatile(
        "mma.sync.aligned.m16n8k8.row.col.f32.tf32.tf32.f32 "
        "{%0,%1,%2,%3}, {%4,%5,%6,%7}, {%8,%9}, {%0,%1,%2,%3};"
        : "+f"(d[0]), "+f"(d[1]), "+f"(d[2]), "+f"(d[3])
        : "r"(a[0]), "r"(a[1]), "r"(a[2]), "r"(a[3]), "r"(b[0]), "r"(b[1]));
}

__global__ void __launch_bounds__(256, 1) gemm_kernel(
    const float* __restrict__ A,   // g_act  [32768,1024] K-major
    const float* __restrict__ B,   // g_wt   [1024,1024]  K-major
    float* __restrict__ C)
{
    extern __shared__ float smem[];
    const int tid  = threadIdx.x;
    const int lane = tid & 31;
    const int w    = tid >> 5;
    const int wm   = w & 3;        // 4 warps along M (64 rows each)
    const int wn   = w >> 2;       // 2 warps along N (64 cols each)
    const int g    = lane >> 2;    // group id (0..7)
    const int t    = lane & 3;     // thread in group (0..3)

    const int m0 = blockIdx.y * BM;
    const int n0 = blockIdx.x * BN;

    float acc[4][8][4];
    #pragma unroll
    for (int i = 0; i < 4; i++)
        #pragma unroll
        for (int j = 0; j < 8; j++)
            #pragma unroll
            for (int q = 0; q < 4; q++) acc[i][j][q] = 0.f;

    const float* Agb = A + (size_t)m0 * 1024;
    const float* Bgb = B + (size_t)n0 * 1024;

    // ---------------- cp.async stage loader ----------------
    auto load_stage = [&](int kt, int s) {
        float* As = smem + s * STAGE_FLOATS;
        float* Bs = As + A_FLOATS;
        const float* Ag = Agb + kt * BK;
        const float* Bg = Bgb + kt * BK;
        #pragma unroll
        for (int i = 0; i < 8; i++) {            // A: 2048 16B chunks / 256 thr
            int ch = tid + i * 256;
            int r = ch >> 3, c = ch & 7;
            cp16(As + r * LDS_ + c * 4, Ag + (size_t)r * 1024 + c * 4);
        }
        #pragma unroll
        for (int i = 0; i < 4; i++) {            // B: 1024 chunks
            int ch = tid + i * 256;
            int r = ch >> 3, c = ch & 7;
            cp16(Bs + r * LDS_ + c * 4, Bg + (size_t)r * 1024 + c * 4);
        }
        cp_commit();
    };

    load_stage(0, 0);
    load_stage(1, 1);

    for (int kt = 0; kt < KTILES; kt++) {
        cp_wait<1>();            // stage kt's group is complete
        __syncthreads();         // make other warps' cp.async stores visible

        if (kt + 2 < KTILES) load_stage(kt + 2, (kt + 2) % STAGES);

        const int s = kt % STAGES;
        const float* As = smem + s * STAGE_FLOATS + (wm * 64) * LDS_;
        const float* Bs = smem + s * STAGE_FLOATS + A_FLOATS + (wn * 64) * LDS_;

        #pragma unroll
        for (int kk = 0; kk < 4; kk++) {
            const int kc = kk * 8 + t;
            uint32_t a[4][4];
            #pragma unroll
            for (int mt = 0; mt < 4; mt++) {
                const float* p = As + (mt * 16 + g) * LDS_ + kc;
                a[mt][0] = __float_as_uint(p[0]);
                a[mt][1] = __float_as_uint(p[8 * LDS_]);
                a[mt][2] = __float_as_uint(p[4]);
                a[mt][3] = __float_as_uint(p[8 * LDS_ + 4]);
            }
            #pragma unroll
            for (int nt = 0; nt < 8; nt++) {
                const float* p = Bs + (nt * 8 + g) * LDS_ + kc;
                uint32_t b[2];
                b[0] = __float_as_uint(p[0]);
                b[1] = __float_as_uint(p[4]);
                #pragma unroll
                for (int mt = 0; mt < 4; mt++)
                    mma_tf32(acc[mt][nt], a[mt], b);
            }
        }
        __syncthreads();         // all warps done with stage s before refill
    }

    // ---------------- epilogue: direct STG.64 ----------------
    #pragma unroll
    for (int mt = 0; mt < 4; mt++) {
        const int row = m0 + wm * 64 + mt * 16 + g;
        #pragma unroll
        for (int nt = 0; nt < 8; nt++) {
            const int col = n0 + wn * 64 + nt * 8 + 2 * t;
            float2 v0 = make_float2(acc[mt][nt][0], acc[mt][nt][1]);
            float2 v1 = make_float2(acc[mt][nt][2], acc[mt][nt][3]);
            *reinterpret_cast<float2*>(&C[(size_t)row * 1024 + col])       = v0;
            *reinterpret_cast<float2*>(&C[(size_t)(row + 8) * 1024 + col]) = v1;
        }
    }
}

// =====================================================================
// Host launcher
// =====================================================================
extern "C" void kernel_launch(void* const* d_in, const int* in_sizes, int n_in,
                              void* d_out, int out_size) {
    const float* x = (const float*)d_in[0];
    const float* w = (const float*)d_in[1];
    if (n_in >= 2 && in_sizes[0] == 1048576 && in_sizes[1] != 1048576) {
        const float* t = x; x = w; w = t;   // defensive order swap
    }
    float* out = (float*)d_out;

    void* act_ptr = nullptr; void* wt_ptr = nullptr;
    cudaGetSymbolAddress(&act_ptr, g_act);
    cudaGetSymbolAddress(&wt_ptr,  g_wt);

    prep_kernel<<<32768, 256>>>(x, (float*)act_ptr);
    wconv_kernel<<<4096, 256>>>(w, (float*)wt_ptr);

    cudaFuncSetAttribute(gemm_kernel,
                         cudaFuncAttributeMaxDynamicSharedMemorySize, SMEM_DYN);
    // grid: x = N tiles (fast-varying -> A slab L2 reuse), y = M tiles
    gemm_kernel<<<dim3(1024 / BN, 32768 / BM), 256, SMEM_DYN>>>(
        (const float*)act_ptr, (const float*)wt_ptr, out);
}

// round 3
// speedup vs baseline: 1.6655x; 1.6655x over previous
#include <cuda_runtime.h>
#include <cuda_fp16.h>
#include <cstdint>

// =====================================================================
// Device scratch (allocation-free: __device__ globals)
// =====================================================================
__device__ __half g_act[33554432];   // 32768 x 1024 fp16: rn(v * x_sp)
__device__ __half g_wt[1048576];     // 1024 x 1024  fp16: rn(weight)

// =====================================================================
// Helpers (base ISA only)
// =====================================================================
__device__ __forceinline__ void cp16(void* s, const void* g) {
    uint32_t sa = (uint32_t)__cvta_generic_to_shared(s);
    asm volatile("cp.async.cg.shared.global [%0], [%1], 16;"
                 :: "r"(sa), "l"(g) : "memory");
}
__device__ __forceinline__ void cp_commit() {
    asm volatile("cp.async.commit_group;" ::: "memory");
}
template <int N>
__device__ __forceinline__ void cp_wait() {
    asm volatile("cp.async.wait_group %0;" :: "n"(N) : "memory");
}
__device__ __forceinline__ void ldsm_x4(uint32_t* r, uint32_t addr) {
    asm volatile("ldmatrix.sync.aligned.m8n8.x4.shared.b16 {%0,%1,%2,%3}, [%4];"
                 : "=r"(r[0]), "=r"(r[1]), "=r"(r[2]), "=r"(r[3]) : "r"(addr));
}
__device__ __forceinline__ void mma_f16(float* d, const uint32_t* a,
                                        const uint32_t* b) {
    asm volatile(
        "mma.sync.aligned.m16n8k16.row.col.f32.f16.f16.f32 "
        "{%0,%1,%2,%3}, {%4,%5,%6,%7}, {%8,%9}, {%0,%1,%2,%3};"
        : "+f"(d[0]), "+f"(d[1]), "+f"(d[2]), "+f"(d[3])
        : "r"(a[0]), "r"(a[1]), "r"(a[2]), "r"(a[3]), "r"(b[0]), "r"(b[1]));
}

// =====================================================================
// Kernel 1: 2:4 prune + variance rescale + fp16 round. One WARP per row.
// =====================================================================
__global__ void __launch_bounds__(256) prep_kernel(const float* __restrict__ x,
                                                   __half* __restrict__ act) {
    const int row  = blockIdx.x * 8 + (threadIdx.x >> 5);
    const int lane = threadIdx.x & 31;
    const float4* src = reinterpret_cast<const float4*>(x + (size_t)row * 1024);

    float p[8][4];
    float s = 0.f, ss = 0.f, ps = 0.f, pss = 0.f;
    #pragma unroll
    for (int j = 0; j < 8; j++) {
        const float4 g = src[lane + 32 * j];
        float v0 = g.x, v1 = g.y, v2 = g.z, v3 = g.w;
        float a0 = fabsf(v0), a1 = fabsf(v1), a2 = fabsf(v2), a3 = fabsf(v3);
        // rank = #elements strictly greater (earlier index wins ties); keep top-2
        int r0 = (a1 >  a0) + (a2 >  a0) + (a3 >  a0);
        int r1 = (a0 >= a1) + (a2 >  a1) + (a3 >  a1);
        int r2 = (a0 >= a2) + (a1 >= a2) + (a3 >  a2);
        int r3 = (a0 >= a3) + (a1 >= a3) + (a2 >= a3);
        p[j][0] = (r0 < 2) ? v0 : 0.f;
        p[j][1] = (r1 < 2) ? v1 : 0.f;
        p[j][2] = (r2 < 2) ? v2 : 0.f;
        p[j][3] = (r3 < 2) ? v3 : 0.f;
        s   += v0 + v1 + v2 + v3;
        ss  += v0*v0 + v1*v1 + v2*v2 + v3*v3;
        ps  += p[j][0] + p[j][1] + p[j][2] + p[j][3];
        pss += p[j][0]*p[j][0] + p[j][1]*p[j][1]
             + p[j][2]*p[j][2] + p[j][3]*p[j][3];
    }
    #pragma unroll
    for (int off = 16; off; off >>= 1) {
        s   += __shfl_xor_sync(0xFFFFFFFFu, s,   off);
        ss  += __shfl_xor_sync(0xFFFFFFFFu, ss,  off);
        ps  += __shfl_xor_sync(0xFFFFFFFFu, ps,  off);
        pss += __shfl_xor_sync(0xFFFFFFFFu, pss, off);
    }
    float varx = (ss  - s  * s  * (1.f / 1024.f)) * (1.f / 1023.f);
    float varp = (pss - ps * ps * (1.f / 1024.f)) * (1.f / 1023.f);
    varp = fmaxf(varp, 1e-9f);
    const float sc = sqrtf(varx / varp);

    uint2* dst = reinterpret_cast<uint2*>(act + (size_t)row * 1024);
    #pragma unroll
    for (int j = 0; j < 8; j++) {
        __half2 h0 = __floats2half2_rn(sc * p[j][0], sc * p[j][1]);
        __half2 h1 = __floats2half2_rn(sc * p[j][2], sc * p[j][3]);
        uint2 o;
        o.x = *reinterpret_cast<uint32_t*>(&h0);
        o.y = *reinterpret_cast<uint32_t*>(&h1);
        dst[lane + 32 * j] = o;
    }
}

// =====================================================================
// Kernel 2: weight fp32 -> fp16
// =====================================================================
__global__ void __launch_bounds__(256) wconv_kernel(const float* __restrict__ w,
                                                    __half* __restrict__ o) {
    int i = blockIdx.x * 256 + threadIdx.x;   // 262144 threads, 4 elts each
    float4 v = reinterpret_cast<const float4*>(w)[i];
    __half2 h0 = __floats2half2_rn(v.x, v.y);
    __half2 h1 = __floats2half2_rn(v.z, v.w);
    uint2 u;
    u.x = *reinterpret_cast<uint32_t*>(&h0);
    u.y = *reinterpret_cast<uint32_t*>(&h1);
    reinterpret_cast<uint2*>(o)[i] = u;
}

// =====================================================================
// Kernel 3: fp16 mma.sync GEMM.  C[32768,1024] = A @ W^T, f32 accumulate.
// CTA 256x128, BK=32, 5-stage cp.async, ONE barrier per k-tile.
// 8 warps, warp tile 64x64. ldmatrix fragments, 80B-padded smem rows
// (conflict-free: r*80 mod 128 covers all eight 16B banks).
// =====================================================================
static constexpr int BM = 256;
static constexpr int BN = 128;
static constexpr int BK = 32;                 // fp16 per row chunk (64B)
static constexpr int STAGES = 5;
static constexpr int LDH = 40;                // padded row stride (fp16 elts, 80B)
static constexpr int A_ELTS = BM * LDH;       // 10240
static constexpr int B_ELTS = BN * LDH;       // 5120
static constexpr int STAGE_ELTS = A_ELTS + B_ELTS;       // 15360
static constexpr unsigned SMEM_DYN = STAGES * STAGE_ELTS * 2;  // 153600 B
static constexpr int KTILES = 1024 / BK;      // 32

__global__ void __launch_bounds__(256, 1) gemm_kernel(
    const __half* __restrict__ A,   // [32768,1024] K-major
    const __half* __restrict__ B,   // [1024,1024]  K-major (W)
    float* __restrict__ C)
{
    extern __shared__ __half smem[];
    const int tid  = threadIdx.x;
    const int lane = tid & 31;
    const int w    = tid >> 5;
    const int wm   = w & 3;         // 4 warps along M (64 rows)
    const int wn   = w >> 2;        // 2 warps along N (64 cols)
    const int g    = lane >> 2;
    const int t    = lane & 3;

    const int m0 = blockIdx.y * BM;
    const int n0 = blockIdx.x * BN;

    float acc[4][8][4];
    #pragma unroll
    for (int i = 0; i < 4; i++)
        #pragma unroll
        for (int j = 0; j < 8; j++)
            #pragma unroll
            for (int q = 0; q < 4; q++) acc[i][j][q] = 0.f;

    const __half* Agb = A + (size_t)m0 * 1024;
    const __half* Bgb = B + (size_t)n0 * 1024;

    const uint32_t smem_base = (uint32_t)__cvta_generic_to_shared(smem);

    // ldmatrix lane-address components (bytes), computed once.
    const int j8 = lane >> 3;        // matrix index 0..3
    const int r8 = lane & 7;         // row within matrix
    // A: matrices (m0-7,k0-7),(m8-15,k0-7),(m0-7,k8-15),(m8-15,k8-15)
    const uint32_t a_lane_off =
        (uint32_t)((wm * 64 + (j8 & 1) * 8 + r8) * 80 + (j8 >> 1) * 16);
    // B: matrices (n0-7,k0-7),(n0-7,k8-15),(n8-15,k0-7),(n8-15,k8-15)
    const uint32_t b_lane_off =
        (uint32_t)(A_ELTS * 2 + (wn * 64 + (j8 >> 1) * 8 + r8) * 80 + (j8 & 1) * 16);

    // ---------------- cp.async stage loader ----------------
    auto load_stage = [&](int kt, int s) {
        __half* As = smem + s * STAGE_ELTS;
        __half* Bs = As + A_ELTS;
        const __half* Ag = Agb + kt * BK;
        const __half* Bg = Bgb + kt * BK;
        #pragma unroll
        for (int i = 0; i < 4; i++) {           // A: 1024 16B chunks
            int ch = tid + i * 256;
            int r = ch >> 2, c = ch & 3;
            cp16(As + r * LDH + c * 8, Ag + (size_t)r * 1024 + c * 8);
        }
        #pragma unroll
        for (int i = 0; i < 2; i++) {           // B: 512 chunks
            int ch = tid + i * 256;
            int r = ch >> 2, c = ch & 3;
            cp16(Bs + r * LDH + c * 8, Bg + (size_t)r * 1024 + c * 8);
        }
        cp_commit();
    };

    load_stage(0, 0);
    load_stage(1, 1);
    load_stage(2, 2);
    load_stage(3, 3);

    for (int kt = 0; kt < KTILES; kt++) {
        cp_wait<3>();            // group kt complete
        __syncthreads();         // all warps' view of stage kt; also gates reuse

        if (kt + 4 < KTILES) load_stage(kt + 4, (kt + 4) % STAGES);

        const uint32_t st = smem_base + (uint32_t)((kt % STAGES) * STAGE_ELTS * 2);
        const uint32_t abase = st + a_lane_off;
        const uint32_t bbase = st + b_lane_off;

        #pragma unroll
        for (int kk = 0; kk < 2; kk++) {
            uint32_t a[4][4];
            #pragma unroll
            for (int mt = 0; mt < 4; mt++)
                ldsm_x4(a[mt], abase + mt * (16 * 80) + kk * 32);
            uint32_t b[4][4];
            #pragma unroll
            for (int np = 0; np < 4; np++)
                ldsm_x4(b[np], bbase + np * (16 * 80) + kk * 32);
            #pragma unroll
            for (int mt = 0; mt < 4; mt++)
                #pragma unroll
                for (int nt = 0; nt < 8; nt++)
                    mma_f16(acc[mt][nt], a[mt], &b[nt >> 1][(nt & 1) * 2]);
        }
    }

    // ---------------- epilogue: direct STG.64 ----------------
    #pragma unroll
    for (int mt = 0; mt < 4; mt++) {
        const int row = m0 + wm * 64 + mt * 16 + g;
        #pragma unroll
        for (int nt = 0; nt < 8; nt++) {
            const int col = n0 + wn * 64 + nt * 8 + 2 * t;
            float2 v0 = make_float2(acc[mt][nt][0], acc[mt][nt][1]);
            float2 v1 = make_float2(acc[mt][nt][2], acc[mt][nt][3]);
            *reinterpret_cast<float2*>(&C[(size_t)row * 1024 + col])       = v0;
            *reinterpret_cast<float2*>(&C[(size_t)(row + 8) * 1024 + col]) = v1;
        }
    }
}

// =====================================================================
// Host launcher
// =====================================================================
extern "C" void kernel_launch(void* const* d_in, const int* in_sizes, int n_in,
                              void* d_out, int out_size) {
    const float* x = (const float*)d_in[0];
    const float* w = (const float*)d_in[1];
    if (n_in >= 2 && in_sizes[0] == 1048576 && in_sizes[1] != 1048576) {
        const float* t = x; x = w; w = t;   // defensive order swap
    }
    float* out = (float*)d_out;

    void* act_ptr = nullptr; void* wt_ptr = nullptr;
    cudaGetSymbolAddress(&act_ptr, g_act);
    cudaGetSymbolAddress(&wt_ptr,  g_wt);

    prep_kernel<<<4096, 256>>>(x, (__half*)act_ptr);
    wconv_kernel<<<1024, 256>>>(w, (__half*)wt_ptr);

    cudaFuncSetAttribute(gemm_kernel,
                         cudaFuncAttributeMaxDynamicSharedMemorySize, SMEM_DYN);
    // grid: x = N tiles (fast -> A slab L2 reuse), y = M tiles
    gemm_kernel<<<dim3(1024 / BN, 32768 / BM), 256, SMEM_DYN>>>(
        (const __half*)act_ptr, (const __half*)wt_ptr, out);
}

// round 5
// speedup vs baseline: 1.9086x; 1.1460x over previous
#include <cuda_runtime.h>
#include <cuda_fp16.h>
#include <cstdint>

// =====================================================================
// Device scratch (allocation-free: __device__ globals)
// =====================================================================
__device__ __half g_act[33554432];   // 32768 x 1024 fp16: rn(v * x_sp)
__device__ __half g_wt[1048576];     // 1024 x 1024  fp16: rn(weight)

// =====================================================================
// Helpers (base ISA only)
// =====================================================================
__device__ __forceinline__ void cp16(void* s, const void* g) {
    uint32_t sa = (uint32_t)__cvta_generic_to_shared(s);
    asm volatile("cp.async.cg.shared.global [%0], [%1], 16;"
                 :: "r"(sa), "l"(g) : "memory");
}
__device__ __forceinline__ void cp_commit() {
    asm volatile("cp.async.commit_group;" ::: "memory");
}
template <int N>
__device__ __forceinline__ void cp_wait() {
    asm volatile("cp.async.wait_group %0;" :: "n"(N) : "memory");
}
__device__ __forceinline__ void ldsm_x4(uint32_t* r, uint32_t addr) {
    asm volatile("ldmatrix.sync.aligned.m8n8.x4.shared.b16 {%0,%1,%2,%3}, [%4];"
                 : "=r"(r[0]), "=r"(r[1]), "=r"(r[2]), "=r"(r[3]) : "r"(addr));
}
__device__ __forceinline__ void mma_f16(float* d, const uint32_t* a,
                                        const uint32_t* b) {
    asm volatile(
        "mma.sync.aligned.m16n8k16.row.col.f32.f16.f16.f32 "
        "{%0,%1,%2,%3}, {%4,%5,%6,%7}, {%8,%9}, {%0,%1,%2,%3};"
        : "+f"(d[0]), "+f"(d[1]), "+f"(d[2]), "+f"(d[3])
        : "r"(a[0]), "r"(a[1]), "r"(a[2]), "r"(a[3]), "r"(b[0]), "r"(b[1]));
}

// =====================================================================
// Kernel 1: 2:4 prune + variance rescale + fp16 round. One WARP per row.
// =====================================================================
__global__ void __launch_bounds__(256) prep_kernel(const float* __restrict__ x,
                                                   __half* __restrict__ act) {
    const int row  = blockIdx.x * 8 + (threadIdx.x >> 5);
    const int lane = threadIdx.x & 31;
    const float4* src = reinterpret_cast<const float4*>(x + (size_t)row * 1024);

    float p[8][4];
    float s = 0.f, ss = 0.f, ps = 0.f, pss = 0.f;
    #pragma unroll
    for (int j = 0; j < 8; j++) {
        const float4 g = src[lane + 32 * j];
        float v0 = g.x, v1 = g.y, v2 = g.z, v3 = g.w;
        float a0 = fabsf(v0), a1 = fabsf(v1), a2 = fabsf(v2), a3 = fabsf(v3);
        // rank = #elements strictly greater (earlier index wins ties); keep top-2
        int r0 = (a1 >  a0) + (a2 >  a0) + (a3 >  a0);
        int r1 = (a0 >= a1) + (a2 >  a1) + (a3 >  a1);
        int r2 = (a0 >= a2) + (a1 >= a2) + (a3 >  a2);
        int r3 = (a0 >= a3) + (a1 >= a3) + (a2 >= a3);
        p[j][0] = (r0 < 2) ? v0 : 0.f;
        p[j][1] = (r1 < 2) ? v1 : 0.f;
        p[j][2] = (r2 < 2) ? v2 : 0.f;
        p[j][3] = (r3 < 2) ? v3 : 0.f;
        s   += v0 + v1 + v2 + v3;
        ss  += v0*v0 + v1*v1 + v2*v2 + v3*v3;
        ps  += p[j][0] + p[j][1] + p[j][2] + p[j][3];
        pss += p[j][0]*p[j][0] + p[j][1]*p[j][1]
             + p[j][2]*p[j][2] + p[j][3]*p[j][3];
    }
    #pragma unroll
    for (int off = 16; off; off >>= 1) {
        s   += __shfl_xor_sync(0xFFFFFFFFu, s,   off);
        ss  += __shfl_xor_sync(0xFFFFFFFFu, ss,  off);
        ps  += __shfl_xor_sync(0xFFFFFFFFu, ps,  off);
        pss += __shfl_xor_sync(0xFFFFFFFFu, pss, off);
    }
    float varx = (ss  - s  * s  * (1.f / 1024.f)) * (1.f / 1023.f);
    float varp = (pss - ps * ps * (1.f / 1024.f)) * (1.f / 1023.f);
    varp = fmaxf(varp, 1e-9f);
    const float sc = sqrtf(varx / varp);

    uint2* dst = reinterpret_cast<uint2*>(act + (size_t)row * 1024);
    #pragma unroll
    for (int j = 0; j < 8; j++) {
        __half2 h0 = __floats2half2_rn(sc * p[j][0], sc * p[j][1]);
        __half2 h1 = __floats2half2_rn(sc * p[j][2], sc * p[j][3]);
        uint2 o;
        o.x = *reinterpret_cast<uint32_t*>(&h0);
        o.y = *reinterpret_cast<uint32_t*>(&h1);
        dst[lane + 32 * j] = o;
    }
}

// =====================================================================
// Kernel 2: weight fp32 -> fp16
// =====================================================================
__global__ void __launch_bounds__(256) wconv_kernel(const float* __restrict__ w,
                                                    __half* __restrict__ o) {
    int i = blockIdx.x * 256 + threadIdx.x;
    float4 v = reinterpret_cast<const float4*>(w)[i];
    __half2 h0 = __floats2half2_rn(v.x, v.y);
    __half2 h1 = __floats2half2_rn(v.z, v.w);
    uint2 u;
    u.x = *reinterpret_cast<uint32_t*>(&h0);
    u.y = *reinterpret_cast<uint32_t*>(&h1);
    reinterpret_cast<uint2*>(o)[i] = u;
}

// =====================================================================
// Kernel 3: fp16 mma.sync GEMM.  C[32768,1024] = A @ W^T, f32 accumulate.
// CTA 128x128, BK=32, 4-stage cp.async, 2 CTAs/SM (4 warps/SMSP).
// 8 warps, warp tile 64x32. ldmatrix fragments, 80B-padded smem rows.
// =====================================================================
static constexpr int BM = 128;
static constexpr int BN = 128;
static constexpr int STAGES = 4;
static constexpr int LDH = 40;                // padded row stride (fp16, 80B)
static constexpr int A_ELTS = BM * LDH;       // 5120
static constexpr int B_ELTS = BN * LDH;       // 5120
static constexpr int STAGE_ELTS = A_ELTS + B_ELTS;        // 10240
static constexpr unsigned SMEM_DYN = STAGES * STAGE_ELTS * 2;  // 81920 B
static constexpr int KTILES = 32;             // K 1024 / 32

__global__ void __launch_bounds__(256, 2) gemm_kernel(
    const __half* __restrict__ A,   // [32768,1024] K-major
    const __half* __restrict__ B,   // [1024,1024]  K-major (W)
    float* __restrict__ C)
{
    extern __shared__ __half smem[];
    const int tid  = threadIdx.x;
    const int lane = tid & 31;
    const int w    = tid >> 5;
    const int wm   = w & 1;         // 2 warps along M (64 rows)
    const int wn   = w >> 1;        // 4 warps along N (32 cols)
    const int g    = lane >> 2;
    const int t    = lane & 3;

    const int m0 = blockIdx.y * BM;
    const int n0 = blockIdx.x * BN;

    float acc[4][4][4];
    #pragma unroll
    for (int i = 0; i < 4; i++)
        #pragma unroll
        for (int j = 0; j < 4; j++)
            #pragma unroll
            for (int q = 0; q < 4; q++) acc[i][j][q] = 0.f;

    const __half* Agb = A + (size_t)m0 * 1024;
    const __half* Bgb = B + (size_t)n0 * 1024;

    const uint32_t smem_base = (uint32_t)__cvta_generic_to_shared(smem);

    const int j8 = lane >> 3;        // ldmatrix matrix index 0..3
    const int r8 = lane & 7;         // row within matrix
    // A: matrices (m0-7,k0-7),(m8-15,k0-7),(m0-7,k8-15),(m8-15,k8-15)
    const uint32_t a_lane_off =
        (uint32_t)((wm * 64 + (j8 & 1) * 8 + r8) * 80 + (j8 >> 1) * 16);
    // B: matrices (n0-7,k0-7),(n0-7,k8-15),(n8-15,k0-7),(n8-15,k8-15)
    const uint32_t b_lane_off =
        (uint32_t)(A_ELTS * 2 + (wn * 32 + (j8 >> 1) * 8 + r8) * 80 + (j8 & 1) * 16);

    // ---------------- cp.async stage loader ----------------
    auto load_stage = [&](int kt, int s) {
        __half* As = smem + s * STAGE_ELTS;
        __half* Bs = As + A_ELTS;
        const __half* Ag = Agb + kt * 32;
        const __half* Bg = Bgb + kt * 32;
        #pragma unroll
        for (int i = 0; i < 2; i++) {           // A: 512 16B chunks
            int ch = tid + i * 256;
            int r = ch >> 2, c = ch & 3;
            cp16(As + r * LDH + c * 8, Ag + (size_t)r * 1024 + c * 8);
        }
        #pragma unroll
        for (int i = 0; i < 2; i++) {           // B: 512 chunks
            int ch = tid + i * 256;
            int r = ch >> 2, c = ch & 3;
            cp16(Bs + r * LDH + c * 8, Bg + (size_t)r * 1024 + c * 8);
        }
        cp_commit();
    };

    load_stage(0, 0);
    load_stage(1, 1);
    load_stage(2, 2);

    for (int kt = 0; kt < KTILES; kt++) {
        cp_wait<2>();            // stage kt's group complete
        __syncthreads();

        if (kt + 3 < KTILES) load_stage(kt + 3, (kt + 3) & 3);

        const uint32_t st = smem_base + (uint32_t)((kt & 3) * STAGE_ELTS * 2);
        const uint32_t abase = st + a_lane_off;
        const uint32_t bbase = st + b_lane_off;

        #pragma unroll
        for (int kk = 0; kk < 2; kk++) {
            uint32_t a[4][4];
            #pragma unroll
            for (int mt = 0; mt < 4; mt++)
                ldsm_x4(a[mt], abase + mt * (16 * 80) + kk * 32);
            uint32_t b[2][4];
            #pragma unroll
            for (int np = 0; np < 2; np++)
                ldsm_x4(b[np], bbase + np * (16 * 80) + kk * 32);
            #pragma unroll
            for (int mt = 0; mt < 4; mt++)
                #pragma unroll
                for (int nt = 0; nt < 4; nt++)
                    mma_f16(acc[mt][nt], a[mt], &b[nt >> 1][(nt & 1) * 2]);
        }
    }

    // ---------------- epilogue: direct STG.64 ----------------
    #pragma unroll
    for (int mt = 0; mt < 4; mt++) {
        const int row = m0 + wm * 64 + mt * 16 + g;
        #pragma unroll
        for (int nt = 0; nt < 4; nt++) {
            const int col = n0 + wn * 32 + nt * 8 + 2 * t;
            float2 v0 = make_float2(acc[mt][nt][0], acc[mt][nt][1]);
            float2 v1 = make_float2(acc[mt][nt][2], acc[mt][nt][3]);
            *reinterpret_cast<float2*>(&C[(size_t)row * 1024 + col])       = v0;
            *reinterpret_cast<float2*>(&C[(size_t)(row + 8) * 1024 + col]) = v1;
        }
    }
}

// =====================================================================
// Host launcher
// =====================================================================
extern "C" void kernel_launch(void* const* d_in, const int* in_sizes, int n_in,
                              void* d_out, int out_size) {
    const float* x = (const float*)d_in[0];
    const float* w = (const float*)d_in[1];
    if (n_in >= 2 && in_sizes[0] == 1048576 && in_sizes[1] != 1048576) {
        const float* t = x; x = w; w = t;   // defensive order swap
    }
    float* out = (float*)d_out;

    void* act_ptr = nullptr; void* wt_ptr = nullptr;
    cudaGetSymbolAddress(&act_ptr, g_act);
    cudaGetSymbolAddress(&wt_ptr,  g_wt);

    prep_kernel<<<4096, 256>>>(x, (__half*)act_ptr);
    wconv_kernel<<<1024, 256>>>(w, (__half*)wt_ptr);

    cudaFuncSetAttribute(gemm_kernel,
                         cudaFuncAttributeMaxDynamicSharedMemorySize, SMEM_DYN);
    // grid: x = N tiles (fast -> A slab L2 reuse), y = M tiles
    gemm_kernel<<<dim3(1024 / BN, 32768 / BM), 256, SMEM_DYN>>>(
        (const __half*)act_ptr, (const __half*)wt_ptr, out);
}